// round 7
// baseline (speedup 1.0000x reference)
#include <cuda_runtime.h>
#include <cstdint>

#define BATCH 256
#define TSTEPS 1024
#define HID 64
#define DIN 3

// Scratch (device globals — no cudaMalloc allowed).
__device__ float g_h2[BATCH * TSTEPS * HID];

typedef unsigned long long u64;

// ---- packed fp32x2 helpers (ptxas never auto-emits FFMA2) ----
__device__ __forceinline__ u64 fma2(u64 a, u64 b, u64 c) {
    u64 d; asm("fma.rn.f32x2 %0, %1, %2, %3;" : "=l"(d) : "l"(a), "l"(b), "l"(c)); return d;
}
__device__ __forceinline__ u64 add2(u64 a, u64 b) {
    u64 d; asm("add.rn.f32x2 %0, %1, %2;" : "=l"(d) : "l"(a), "l"(b)); return d;
}
__device__ __forceinline__ u64 packf2(float lo, float hi) {
    u64 d; asm("mov.b64 %0, {%1, %2};" : "=l"(d) : "f"(lo), "f"(hi)); return d;
}
__device__ __forceinline__ float2 unpackf2(u64 v) {
    float2 f; asm("mov.b64 {%0, %1}, %2;" : "=f"(f.x), "=f"(f.y) : "l"(v)); return f;
}
// 16B shared load straight into two 64-bit regs
__device__ __forceinline__ void lds2(u64 &a, u64 &b, uint32_t addr) {
    asm volatile("ld.shared.v2.b64 {%0, %1}, [%2];" : "=l"(a), "=l"(b) : "r"(addr));
}

__device__ __forceinline__ float sigf(float x) {
    float e = __expf(-x);
    return __fdividef(1.0f, 1.0f + e);
}
__device__ __forceinline__ float tanhf_(float x) {
    float ax = fabsf(x);
    float e = __expf(-2.0f * ax);
    float r = __fdividef(1.0f - e, 1.0f + e);
    return copysignf(r, x);
}

// ============================================================================
// Fused 2-layer LSTM. One CTA per 2 sequences, 256 threads.
// Thread j owns gate row j of Whh0 (w0), Wih1 (wA), Whh1 (wB) in registers.
// Pipeline: iteration t computes layer1 step t and layer2 step t-2 (lag 2).
//   h1 ring[4]: A-dots (Whh0) read h1[t-1] (slot (t+3)&3);
//               B-dots (Wih1) read h1[t-2] (slot (t+2)&3).
//   h2 ring[2]: C-dots (Whh1) read h2[t-3] (slot (t+1)&1).
// B-dots run BEFORE the h-barrier: h1[t-2] was written at cell(t-2), which is
// separated from B-dots(t) by TWO barriers (h-barrier(t-1), gate-barrier(t-1)).
// Gates stored transposed [m*4+g] so cell phase reads i,f,g,o in ONE LDS.128.
// Cell phase: 256 threads = 256 cells (unit = tid>>6: l1s0,l1s1,l2s0,l2s1).
// ============================================================================
__global__ void __launch_bounds__(256, 1) lstm_fused(
    const float* __restrict__ x,
    const float* __restrict__ Wih0, const float* __restrict__ Whh0,
    const float* __restrict__ bih0, const float* __restrict__ bhh0,
    const float* __restrict__ Wih1, const float* __restrict__ Whh1,
    const float* __restrict__ bih1, const float* __restrict__ bhh1)
{
    __shared__ __align__(16) float sx[2][TSTEPS * DIN];  // 24 KB
    __shared__ __align__(16) float h1r[4][2][HID];       // 4 KB ring
    __shared__ __align__(16) float h2r[2][2][HID];       // 2 KB ring
    __shared__ __align__(16) float sgl1[2][256];         // transposed gates l1
    __shared__ __align__(16) float sgl2[2][256];         // transposed gates l2
    const int tid = threadIdx.x;
    const int b0 = blockIdx.x * 2;

    // stage both sequences' inputs
    {
        const float4* xs0 = (const float4*)(x + (size_t)b0 * TSTEPS * DIN);
        const float4* xs1 = (const float4*)(x + (size_t)(b0 + 1) * TSTEPS * DIN);
        #pragma unroll
        for (int i = 0; i < 3; i++) {
            int idx = tid + i * 256;
            ((float4*)sx[0])[idx] = xs0[idx];
            ((float4*)sx[1])[idx] = xs1[idx];
        }
    }
    // zero ALL ring slots (h1: 1024 floats, h2: 512 floats)
    #pragma unroll
    for (int i = 0; i < 4; i++) ((float*)h1r)[tid + i * 256] = 0.0f;
    #pragma unroll
    for (int i = 0; i < 2; i++) ((float*)h2r)[tid + i * 256] = 0.0f;

    // per-thread weight rows, packed f32x2 along k
    u64 w0[32], wA[32], wB[32];
    {
        const float4* r0 = (const float4*)(Whh0 + tid * HID);
        const float4* rA = (const float4*)(Wih1 + tid * HID);
        const float4* rB = (const float4*)(Whh1 + tid * HID);
        #pragma unroll
        for (int i = 0; i < 16; i++) {
            float4 v = r0[i]; w0[2*i] = packf2(v.x, v.y); w0[2*i+1] = packf2(v.z, v.w);
            float4 a = rA[i]; wA[2*i] = packf2(a.x, a.y); wA[2*i+1] = packf2(a.z, a.w);
            float4 b = rB[i]; wB[2*i] = packf2(b.x, b.y); wB[2*i+1] = packf2(b.z, b.w);
        }
    }
    const float wx0 = Wih0[tid * 3 + 0], wx1 = Wih0[tid * 3 + 1], wx2 = Wih0[tid * 3 + 2];
    const float bias0 = bih0[tid] + bhh0[tid];
    const float bias1 = bih1[tid] + bhh1[tid];
    const int gtype = tid >> 6;           // gate row group (warp-uniform)
    const int gm = tid & 63;              // row within gate

    // cell role: unit = tid>>6 (0=l1s0, 1=l1s1, 2=l2s0, 3=l2s1), m = tid&63
    const int cl_unit = tid >> 6;
    const int cl_l2 = cl_unit >> 1;
    const int cl_b = cl_unit & 1;
    const int cl_m = tid & 63;
    float c = 0.0f;

    const uint32_t A_h1 = (uint32_t)__cvta_generic_to_shared(&h1r[0][0][0]);
    const uint32_t A_h2 = (uint32_t)__cvta_generic_to_shared(&h2r[0][0][0]);
    // cell h write base (slot added per-iteration)
    const uint32_t a_wr_h1 = A_h1 + (uint32_t)cl_b * 256u + (uint32_t)cl_m * 4u;
    const uint32_t a_wr_h2 = A_h2 + (uint32_t)cl_b * 256u + (uint32_t)cl_m * 4u;
    float* h2out = &g_h2[(size_t)(b0 + cl_b) * TSTEPS * HID + cl_m];
    // cell gate read (transposed, float4)
    const float* cg_l1 = &sgl1[cl_b][cl_m * 4];
    const float* cg_l2 = &sgl2[cl_b][cl_m * 4];
    __syncthreads();

    #pragma unroll 1
    for (int t = 0; t < TSTEPS + 2; t++) {
        const uint32_t slotA = ((uint32_t)(t + 3) & 3u) * 512u;  // h1[t-1]
        const uint32_t slotB = ((uint32_t)(t + 2) & 3u) * 512u;  // h1[t-2]
        const uint32_t slotC = ((uint32_t)(t + 1) & 1u) * 512u;  // h2[t-3]

        // ---- B-dots (Wih1 · h1[t-2]) BEFORE h-barrier (data 2 barriers old)
        u64 B0 = packf2(bias1, 0.0f), B1 = 0;
        {
            const uint32_t hb0 = A_h1 + slotB, hb1 = hb0 + 256;
            #pragma unroll
            for (int kk = 0; kk < 16; kk++) {
                u64 p0, p1, q0, q1;
                lds2(p0, p1, hb0 + kk * 16);
                lds2(q0, q1, hb1 + kk * 16);
                B0 = fma2(wA[2*kk], p0, B0); B0 = fma2(wA[2*kk+1], p1, B0);
                B1 = fma2(wA[2*kk], q0, B1); B1 = fma2(wA[2*kk+1], q1, B1);
            }
        }
        __syncthreads();   // h-barrier: h1[t-1], h2[t-3] now visible

        // ---- A-dots (Whh0 · h1[t-1]) + C-dots (Whh1 · h2[t-3]) ----
        const int tx = (t < TSTEPS) ? t : (TSTEPS - 1);
        float xa = bias0 + wx0*sx[0][tx*3] + wx1*sx[0][tx*3+1] + wx2*sx[0][tx*3+2];
        float xb = bias0 + wx0*sx[1][tx*3] + wx1*sx[1][tx*3+1] + wx2*sx[1][tx*3+2];
        u64 A0 = packf2(xa, 0.0f), A1 = packf2(xb, 0.0f), C0 = 0, C1 = 0;
        {
            const uint32_t ha0 = A_h1 + slotA, ha1 = ha0 + 256;
            const uint32_t hc0 = A_h2 + slotC, hc1 = hc0 + 256;
            #pragma unroll
            for (int kk = 0; kk < 16; kk++) {
                u64 p0, p1, q0, q1, r0, r1, s0, s1;
                lds2(p0, p1, ha0 + kk * 16);
                lds2(q0, q1, ha1 + kk * 16);
                lds2(r0, r1, hc0 + kk * 16);
                lds2(s0, s1, hc1 + kk * 16);
                A0 = fma2(w0[2*kk],   p0, A0); A0 = fma2(w0[2*kk+1], p1, A0);
                A1 = fma2(w0[2*kk],   q0, A1); A1 = fma2(w0[2*kk+1], q1, A1);
                C0 = fma2(wB[2*kk],   r0, C0); C0 = fma2(wB[2*kk+1], r1, C0);
                C1 = fma2(wB[2*kk],   s0, C1); C1 = fma2(wB[2*kk+1], s1, C1);
            }
        }
        float2 fA0 = unpackf2(A0), fA1 = unpackf2(A1);
        float2 f20 = unpackf2(add2(B0, C0));
        float2 f21 = unpackf2(add2(B1, C1));
        float pre10 = fA0.x + fA0.y;
        float pre11 = fA1.x + fA1.y;
        float pre20 = f20.x + f20.y;
        float pre21 = f21.x + f21.y + bias1;
        float v10, v11, v20, v21;
        if (gtype == 2) {
            v10 = tanhf_(pre10); v11 = tanhf_(pre11);
            v20 = tanhf_(pre20); v21 = tanhf_(pre21);
        } else {
            v10 = sigf(pre10); v11 = sigf(pre11);
            v20 = sigf(pre20); v21 = sigf(pre21);
        }
        // transposed gate stores: [m*4 + g] (4-way STS conflict, pre-barrier)
        sgl1[0][gm * 4 + gtype] = v10;
        sgl1[1][gm * 4 + gtype] = v11;
        sgl2[0][gm * 4 + gtype] = v20;
        sgl2[1][gm * 4 + gtype] = v21;
        __syncthreads();   // gate barrier

        // ---- cell phase: one cell per thread; gates via ONE LDS.128 ----
        const bool active = cl_l2 ? (t >= 2) : (t < TSTEPS);
        if (active) {
            float4 gv4 = cl_l2 ? *(const float4*)cg_l2 : *(const float4*)cg_l1;
            c = fmaf(gv4.y, c, gv4.x * gv4.z);     // c = f*c + i*g
            float hn = gv4.w * tanhf_(c);          // h = o*tanh(c)
            if (cl_l2) {
                asm volatile("st.shared.f32 [%0], %1;"
                             :: "r"(a_wr_h2 + ((uint32_t)(t & 1)) * 512u), "f"(hn) : "memory");
                h2out[(size_t)(t - 2) * HID] = hn;
            } else {
                asm volatile("st.shared.f32 [%0], %1;"
                             :: "r"(a_wr_h1 + ((uint32_t)(t & 3)) * 512u), "f"(hn) : "memory");
            }
        }
        // h writes of this iteration become visible at next iteration's
        // h-barrier; B-dots(t+1) only touch data >=2 barriers old.
    }
}

// ============================================================================
// Output projection: y[r, 0..2] = W_out · h2[r] + b_out.
// ============================================================================
__global__ void __launch_bounds__(256) proj_kernel(
    const float* __restrict__ Wout, const float* __restrict__ bout,
    float* __restrict__ y)
{
    __shared__ float sw[3 * 64];
    __shared__ float sb[3];
    const int tid = threadIdx.x;
    if (tid < 192) sw[tid] = Wout[tid];
    if (tid < 3)   sb[tid] = bout[tid];
    __syncthreads();

    int gg = blockIdx.x * 256 + tid;
    int r = gg >> 4;
    int seg = gg & 15;
    float4 v = *(const float4*)&g_h2[(size_t)r * HID + seg * 4];
    int s4 = seg * 4;
    float a0 = sw[s4] * v.x + sw[s4+1] * v.y + sw[s4+2] * v.z + sw[s4+3] * v.w;
    float a1 = sw[64+s4] * v.x + sw[64+s4+1] * v.y + sw[64+s4+2] * v.z + sw[64+s4+3] * v.w;
    float a2 = sw[128+s4] * v.x + sw[128+s4+1] * v.y + sw[128+s4+2] * v.z + sw[128+s4+3] * v.w;
    #pragma unroll
    for (int o = 8; o > 0; o >>= 1) {
        a0 += __shfl_xor_sync(0xffffffffu, a0, o);
        a1 += __shfl_xor_sync(0xffffffffu, a1, o);
        a2 += __shfl_xor_sync(0xffffffffu, a2, o);
    }
    if (seg == 0) {
        y[(size_t)r * 3 + 0] = a0 + sb[0];
        y[(size_t)r * 3 + 1] = a1 + sb[1];
        y[(size_t)r * 3 + 2] = a2 + sb[2];
    }
}

extern "C" void kernel_launch(void* const* d_in, const int* in_sizes, int n_in,
                              void* d_out, int out_size)
{
    const float* x    = (const float*)d_in[0];
    const float* Wih0 = (const float*)d_in[1];
    const float* Whh0 = (const float*)d_in[2];
    const float* bih0 = (const float*)d_in[3];
    const float* bhh0 = (const float*)d_in[4];
    const float* Wih1 = (const float*)d_in[5];
    const float* Whh1 = (const float*)d_in[6];
    const float* bih1 = (const float*)d_in[7];
    const float* bhh1 = (const float*)d_in[8];
    const float* Wout = (const float*)d_in[9];
    const float* bout = (const float*)d_in[10];
    float* y = (float*)d_out;

    lstm_fused<<<BATCH / 2, 256>>>(x, Wih0, Whh0, bih0, bhh0,
                                   Wih1, Whh1, bih1, bhh1);
    proj_kernel<<<(BATCH * TSTEPS * 16) / 256, 256>>>(Wout, bout, y);
}

// round 8
// speedup vs baseline: 1.2608x; 1.2608x over previous
#include <cuda_runtime.h>
#include <cstdint>

#define BATCH 256
#define TSTEPS 1024
#define HID 64
#define DIN 3

typedef unsigned long long u64;

// ---- packed fp32x2 helpers (ptxas never auto-emits FFMA2) ----
__device__ __forceinline__ u64 fma2(u64 a, u64 b, u64 c) {
    u64 d; asm("fma.rn.f32x2 %0, %1, %2, %3;" : "=l"(d) : "l"(a), "l"(b), "l"(c)); return d;
}
__device__ __forceinline__ u64 add2(u64 a, u64 b) {
    u64 d; asm("add.rn.f32x2 %0, %1, %2;" : "=l"(d) : "l"(a), "l"(b)); return d;
}
__device__ __forceinline__ u64 packf2(float lo, float hi) {
    u64 d; asm("mov.b64 %0, {%1, %2};" : "=l"(d) : "f"(lo), "f"(hi)); return d;
}
__device__ __forceinline__ float2 unpackf2(u64 v) {
    float2 f; asm("mov.b64 {%0, %1}, %2;" : "=f"(f.x), "=f"(f.y) : "l"(v)); return f;
}
// 16B shared load straight into two 64-bit regs
__device__ __forceinline__ void lds2(u64 &a, u64 &b, uint32_t addr) {
    asm volatile("ld.shared.v2.b64 {%0, %1}, [%2];" : "=l"(a), "=l"(b) : "r"(addr));
}

__device__ __forceinline__ float sigf(float x) {
    float e = __expf(-x);
    return __fdividef(1.0f, 1.0f + e);
}
__device__ __forceinline__ float tanhf_(float x) {
    float ax = fabsf(x);
    float e = __expf(-2.0f * ax);
    float r = __fdividef(1.0f - e, 1.0f + e);
    return copysignf(r, x);
}

// ============================================================================
// Fused 2-layer LSTM + output projection. One CTA per 2 sequences, 256 thr.
// EXACT round-2 recurrence structure (validated 861us):
//   thread j owns gate row j of Whh0/Wih1/Whh1 in registers;
//   iter t computes layer1 step t and layer2 step t-1;
//   sh1 = h1[t-1], sh2 = h2[t-2]; gate smem exchange; 2 barriers/step;
//   cell phase: 256 threads = 256 cells.
// NEW: h2 staged in padded smem tile st2[2][32][65]; every 32 steps, 192
// threads each compute one y[b][t][o] = Wout[o]·h2[b][t] + bout[o] directly
// to global — the separate projection kernel and its 100MB of DRAM traffic
// are eliminated.
// ============================================================================
__global__ void __launch_bounds__(256, 1) lstm_fused(
    const float* __restrict__ x,
    const float* __restrict__ Wih0, const float* __restrict__ Whh0,
    const float* __restrict__ bih0, const float* __restrict__ bhh0,
    const float* __restrict__ Wih1, const float* __restrict__ Whh1,
    const float* __restrict__ bih1, const float* __restrict__ bhh1,
    const float* __restrict__ Wout, const float* __restrict__ bout,
    float* __restrict__ y)
{
    __shared__ __align__(16) float sx[2][TSTEPS * DIN];  // 24 KB
    __shared__ __align__(16) float sh1[2][HID];
    __shared__ __align__(16) float sh2[2][HID];
    __shared__ __align__(16) float sg1[2][256];
    __shared__ __align__(16) float sg2[2][256];
    __shared__ __align__(16) float st2[2][32][65];       // h2 stage, padded
    __shared__ float sw[192];
    __shared__ float sb[3];
    const int tid = threadIdx.x;
    const int b0 = blockIdx.x * 2;

    // stage both sequences' inputs + projection weights
    {
        const float4* xs0 = (const float4*)(x + (size_t)b0 * TSTEPS * DIN);
        const float4* xs1 = (const float4*)(x + (size_t)(b0 + 1) * TSTEPS * DIN);
        #pragma unroll
        for (int i = 0; i < 3; i++) {
            int idx = tid + i * 256;
            ((float4*)sx[0])[idx] = xs0[idx];
            ((float4*)sx[1])[idx] = xs1[idx];
        }
        if (tid < 192) sw[tid] = Wout[tid];
        if (tid < 3)   sb[tid] = bout[tid];
    }

    // per-thread weight rows, packed f32x2 along k
    u64 w0[32], wA[32], wB[32];
    {
        const float4* r0 = (const float4*)(Whh0 + tid * HID);
        const float4* rA = (const float4*)(Wih1 + tid * HID);
        const float4* rB = (const float4*)(Whh1 + tid * HID);
        #pragma unroll
        for (int i = 0; i < 16; i++) {
            float4 v = r0[i]; w0[2*i] = packf2(v.x, v.y); w0[2*i+1] = packf2(v.z, v.w);
            float4 a = rA[i]; wA[2*i] = packf2(a.x, a.y); wA[2*i+1] = packf2(a.z, a.w);
            float4 b = rB[i]; wB[2*i] = packf2(b.x, b.y); wB[2*i+1] = packf2(b.z, b.w);
        }
    }
    const float wx0 = Wih0[tid * 3 + 0], wx1 = Wih0[tid * 3 + 1], wx2 = Wih0[tid * 3 + 2];
    const float bias0 = bih0[tid] + bhh0[tid];
    const float bias1 = bih1[tid] + bhh1[tid];
    const int gtype = tid >> 6;

    // cell role: tid -> (layer, seq, m)
    const int cl_layer = tid >> 7;
    const int cl_b = (tid >> 6) & 1;
    const int cl_m = tid & 63;
    float c = 0.0f;

    if (tid < 128) ((float*)sh1)[tid] = 0.0f;
    else           ((float*)sh2)[tid - 128] = 0.0f;

    const uint32_t a_h1s0 = (uint32_t)__cvta_generic_to_shared(&sh1[0][0]);
    const uint32_t a_h1s1 = (uint32_t)__cvta_generic_to_shared(&sh1[1][0]);
    const uint32_t a_h2s0 = (uint32_t)__cvta_generic_to_shared(&sh2[0][0]);
    const uint32_t a_h2s1 = (uint32_t)__cvta_generic_to_shared(&sh2[1][0]);

    // projection role (threads 0..191): pb = seq, po = output, ptt = local t
    const int pb = tid / 96;
    const int pr = tid % 96;
    const int po = pr >> 5;
    const int ptt = pr & 31;
    const float* pwrow = &sw[po * 64];
    __syncthreads();

    #pragma unroll 1
    for (int t = 0; t <= TSTEPS; t++) {
        // ---- gate phase: 6 dot products, 192 fma2, 64 LDS.128 (broadcast) --
        u64 A0 = 0, A1 = 0, B0 = 0, B1 = 0, C0 = 0, C1 = 0;
        #pragma unroll
        for (int kk = 0; kk < 16; kk++) {
            u64 p0, p1, q0, q1, r0, r1, s0, s1;
            lds2(p0, p1, a_h1s0 + kk * 16);
            lds2(q0, q1, a_h1s1 + kk * 16);
            lds2(r0, r1, a_h2s0 + kk * 16);
            lds2(s0, s1, a_h2s1 + kk * 16);
            B0 = fma2(wA[2*kk],   p0, B0); B0 = fma2(wA[2*kk+1], p1, B0);
            B1 = fma2(wA[2*kk],   q0, B1); B1 = fma2(wA[2*kk+1], q1, B1);
            C0 = fma2(wB[2*kk],   r0, C0); C0 = fma2(wB[2*kk+1], r1, C0);
            C1 = fma2(wB[2*kk],   s0, C1); C1 = fma2(wB[2*kk+1], s1, C1);
            A0 = fma2(w0[2*kk],   p0, A0); A0 = fma2(w0[2*kk+1], p1, A0);
            A1 = fma2(w0[2*kk],   q0, A1); A1 = fma2(w0[2*kk+1], q1, A1);
        }
        // l2 preacts first: their MUFU chains overlap the l1 scalar adds
        float2 f20 = unpackf2(add2(B0, C0));
        float2 f21 = unpackf2(add2(B1, C1));
        float pre20 = f20.x + f20.y + bias1;
        float pre21 = f21.x + f21.y + bias1;
        float v20, v21;
        if (gtype == 2) { v20 = tanhf_(pre20); v21 = tanhf_(pre21); }
        else            { v20 = sigf(pre20);   v21 = sigf(pre21);   }
        sg2[0][tid] = v20; sg2[1][tid] = v21;

        const int tx = (t < TSTEPS) ? t : (TSTEPS - 1);
        float2 fA0 = unpackf2(A0), fA1 = unpackf2(A1);
        float xa0 = sx[0][tx*3 + 0], xa1 = sx[0][tx*3 + 1], xa2 = sx[0][tx*3 + 2];
        float xb0 = sx[1][tx*3 + 0], xb1 = sx[1][tx*3 + 1], xb2 = sx[1][tx*3 + 2];
        float pre10 = fA0.x + fA0.y + bias0 + wx0*xa0 + wx1*xa1 + wx2*xa2;
        float pre11 = fA1.x + fA1.y + bias0 + wx0*xb0 + wx1*xb1 + wx2*xb2;
        float v10, v11;
        if (gtype == 2) { v10 = tanhf_(pre10); v11 = tanhf_(pre11); }
        else            { v10 = sigf(pre10);   v11 = sigf(pre11);   }
        sg1[0][tid] = v10; sg1[1][tid] = v11;
        __syncthreads();

        // ---- cell phase: one cell per thread (warp-uniform roles) ----
        bool active = cl_layer ? (t >= 1) : (t < TSTEPS);
        if (active) {
            const float* Gp = cl_layer ? sg2[cl_b] : sg1[cl_b];
            float iv = Gp[cl_m], fv = Gp[cl_m + 64];
            float gv = Gp[cl_m + 128], ov = Gp[cl_m + 192];
            c = fmaf(fv, c, iv * gv);
            float hn = ov * tanhf_(c);
            if (cl_layer) {
                sh2[cl_b][cl_m] = hn;
                st2[cl_b][(t - 1) & 31][cl_m] = hn;   // stage for projection
            } else {
                sh1[cl_b][cl_m] = hn;
            }
        }
        __syncthreads();

        // ---- projection flush: every 32 steps, after the barrier that makes
        // all st2 writes (l2 steps t-32..t-1) visible. Next st2 write to any
        // flushed slot happens only after barrier1 of iter t+1. ----
        if ((t & 31) == 0 && t > 0 && tid < 192) {
            const float* hrow = &st2[pb][ptt][0];
            float acc = sb[po];
            #pragma unroll 16
            for (int k = 0; k < 64; k++)
                acc = fmaf(pwrow[k], hrow[k], acc);
            y[((size_t)(b0 + pb) * TSTEPS + (size_t)(t - 32 + ptt)) * 3 + po] = acc;
        }
    }
}

extern "C" void kernel_launch(void* const* d_in, const int* in_sizes, int n_in,
                              void* d_out, int out_size)
{
    const float* x    = (const float*)d_in[0];
    const float* Wih0 = (const float*)d_in[1];
    const float* Whh0 = (const float*)d_in[2];
    const float* bih0 = (const float*)d_in[3];
    const float* bhh0 = (const float*)d_in[4];
    const float* Wih1 = (const float*)d_in[5];
    const float* Whh1 = (const float*)d_in[6];
    const float* bih1 = (const float*)d_in[7];
    const float* bhh1 = (const float*)d_in[8];
    const float* Wout = (const float*)d_in[9];
    const float* bout = (const float*)d_in[10];
    float* y = (float*)d_out;

    lstm_fused<<<BATCH / 2, 256>>>(x, Wih0, Whh0, bih0, bhh0,
                                   Wih1, Whh1, bih1, bhh1,
                                   Wout, bout, y);
}

// round 9
// speedup vs baseline: 1.3538x; 1.0738x over previous
#include <cuda_runtime.h>
#include <cuda_fp16.h>
#include <cstdint>

#define BATCH 256
#define TSTEPS 1024
#define HID 64
#define DIN 3

// Scratch (device globals — no cudaMalloc allowed). h2 stored as fp16:
// halves projection-kernel DRAM traffic; 2^-11 rounding on h2 -> ~3e-4 on y.
__device__ __half g_h2[BATCH * TSTEPS * HID];

typedef unsigned long long u64;

// ---- packed fp32x2 helpers (ptxas never auto-emits FFMA2) ----
__device__ __forceinline__ u64 fma2(u64 a, u64 b, u64 c) {
    u64 d; asm("fma.rn.f32x2 %0, %1, %2, %3;" : "=l"(d) : "l"(a), "l"(b), "l"(c)); return d;
}
__device__ __forceinline__ u64 add2(u64 a, u64 b) {
    u64 d; asm("add.rn.f32x2 %0, %1, %2;" : "=l"(d) : "l"(a), "l"(b)); return d;
}
__device__ __forceinline__ u64 packf2(float lo, float hi) {
    u64 d; asm("mov.b64 %0, {%1, %2};" : "=l"(d) : "f"(lo), "f"(hi)); return d;
}
__device__ __forceinline__ float2 unpackf2(u64 v) {
    float2 f; asm("mov.b64 {%0, %1}, %2;" : "=f"(f.x), "=f"(f.y) : "l"(v)); return f;
}
// 16B shared load straight into two 64-bit regs
__device__ __forceinline__ void lds2(u64 &a, u64 &b, uint32_t addr) {
    asm volatile("ld.shared.v2.b64 {%0, %1}, [%2];" : "=l"(a), "=l"(b) : "r"(addr));
}

__device__ __forceinline__ float sigf(float x) {
    float e = __expf(-x);
    return __fdividef(1.0f, 1.0f + e);
}
__device__ __forceinline__ float tanhf_(float x) {
    float ax = fabsf(x);
    float e = __expf(-2.0f * ax);
    float r = __fdividef(1.0f - e, 1.0f + e);
    return copysignf(r, x);
}

// ============================================================================
// Fused 2-layer LSTM — EXACT round-2 champion structure (861us validated).
// One CTA per 2 sequences, 256 threads. Thread j owns gate row j of
// Whh0, Wih1, Whh1 (all in registers). Pipeline: iter t = layer1 step t,
// layer2 step t-1. sh1 = h1[t-1], sh2 = h2[t-2]. Gate exchange via smem,
// 2 barriers/step. Cell phase: 256 threads = 256 cells.
// Only change vs champion: h2 written to global as fp16.
// ============================================================================
__global__ void __launch_bounds__(256, 1) lstm_fused(
    const float* __restrict__ x,
    const float* __restrict__ Wih0, const float* __restrict__ Whh0,
    const float* __restrict__ bih0, const float* __restrict__ bhh0,
    const float* __restrict__ Wih1, const float* __restrict__ Whh1,
    const float* __restrict__ bih1, const float* __restrict__ bhh1)
{
    __shared__ __align__(16) float sx[2][TSTEPS * DIN];  // 24 KB
    __shared__ __align__(16) float sh1[2][HID];
    __shared__ __align__(16) float sh2[2][HID];
    __shared__ __align__(16) float sg1[2][256];
    __shared__ __align__(16) float sg2[2][256];
    const int tid = threadIdx.x;
    const int b0 = blockIdx.x * 2;

    // stage both sequences' inputs
    {
        const float4* xs0 = (const float4*)(x + (size_t)b0 * TSTEPS * DIN);
        const float4* xs1 = (const float4*)(x + (size_t)(b0 + 1) * TSTEPS * DIN);
        #pragma unroll
        for (int i = 0; i < 3; i++) {
            int idx = tid + i * 256;
            ((float4*)sx[0])[idx] = xs0[idx];
            ((float4*)sx[1])[idx] = xs1[idx];
        }
    }

    // per-thread weight rows, packed f32x2 along k
    u64 w0[32], wA[32], wB[32];
    {
        const float4* r0 = (const float4*)(Whh0 + tid * HID);
        const float4* rA = (const float4*)(Wih1 + tid * HID);
        const float4* rB = (const float4*)(Whh1 + tid * HID);
        #pragma unroll
        for (int i = 0; i < 16; i++) {
            float4 v = r0[i]; w0[2*i] = packf2(v.x, v.y); w0[2*i+1] = packf2(v.z, v.w);
            float4 a = rA[i]; wA[2*i] = packf2(a.x, a.y); wA[2*i+1] = packf2(a.z, a.w);
            float4 b = rB[i]; wB[2*i] = packf2(b.x, b.y); wB[2*i+1] = packf2(b.z, b.w);
        }
    }
    const float wx0 = Wih0[tid * 3 + 0], wx1 = Wih0[tid * 3 + 1], wx2 = Wih0[tid * 3 + 2];
    const float bias0 = bih0[tid] + bhh0[tid];
    const float bias1 = bih1[tid] + bhh1[tid];
    const int gtype = tid >> 6;

    // cell role: tid -> (layer, seq, m)
    const int cl_layer = tid >> 7;
    const int cl_b = (tid >> 6) & 1;
    const int cl_m = tid & 63;
    float c = 0.0f;

    if (tid < 128) ((float*)sh1)[tid] = 0.0f;
    else           ((float*)sh2)[tid - 128] = 0.0f;

    const uint32_t a_h1s0 = (uint32_t)__cvta_generic_to_shared(&sh1[0][0]);
    const uint32_t a_h1s1 = (uint32_t)__cvta_generic_to_shared(&sh1[1][0]);
    const uint32_t a_h2s0 = (uint32_t)__cvta_generic_to_shared(&sh2[0][0]);
    const uint32_t a_h2s1 = (uint32_t)__cvta_generic_to_shared(&sh2[1][0]);
    __half* h2out = &g_h2[(size_t)(b0 + cl_b) * TSTEPS * HID + cl_m];
    __syncthreads();

    #pragma unroll 1
    for (int t = 0; t <= TSTEPS; t++) {
        // ---- gate phase: 6 dot products, 192 fma2, 64 LDS.128 (all broadcast)
        u64 A0 = 0, A1 = 0, B0 = 0, B1 = 0, C0 = 0, C1 = 0;
        #pragma unroll
        for (int kk = 0; kk < 16; kk++) {
            u64 p0, p1, q0, q1, r0, r1, s0, s1;
            lds2(p0, p1, a_h1s0 + kk * 16);
            lds2(q0, q1, a_h1s1 + kk * 16);
            lds2(r0, r1, a_h2s0 + kk * 16);
            lds2(s0, s1, a_h2s1 + kk * 16);
            A0 = fma2(w0[2*kk],     p0, A0);
            A0 = fma2(w0[2*kk + 1], p1, A0);
            A1 = fma2(w0[2*kk],     q0, A1);
            A1 = fma2(w0[2*kk + 1], q1, A1);
            B0 = fma2(wA[2*kk],     p0, B0);
            B0 = fma2(wA[2*kk + 1], p1, B0);
            B1 = fma2(wA[2*kk],     q0, B1);
            B1 = fma2(wA[2*kk + 1], q1, B1);
            C0 = fma2(wB[2*kk],     r0, C0);
            C0 = fma2(wB[2*kk + 1], r1, C0);
            C1 = fma2(wB[2*kk],     s0, C1);
            C1 = fma2(wB[2*kk + 1], s1, C1);
        }
        const int tx = (t < TSTEPS) ? t : (TSTEPS - 1);
        float xa0 = sx[0][tx*3 + 0], xa1 = sx[0][tx*3 + 1], xa2 = sx[0][tx*3 + 2];
        float xb0 = sx[1][tx*3 + 0], xb1 = sx[1][tx*3 + 1], xb2 = sx[1][tx*3 + 2];
        float2 fA0 = unpackf2(A0), fA1 = unpackf2(A1);
        float2 fB0 = unpackf2(B0), fB1 = unpackf2(B1);
        float2 fC0 = unpackf2(C0), fC1 = unpackf2(C1);
        float pre10 = fA0.x + fA0.y + bias0 + wx0*xa0 + wx1*xa1 + wx2*xa2;
        float pre11 = fA1.x + fA1.y + bias0 + wx0*xb0 + wx1*xb1 + wx2*xb2;
        float pre20 = (fB0.x + fB0.y) + (fC0.x + fC0.y) + bias1;
        float pre21 = (fB1.x + fB1.y) + (fC1.x + fC1.y) + bias1;
        float v10, v11, v20, v21;
        if (gtype == 2) {
            v10 = tanhf_(pre10); v11 = tanhf_(pre11);
            v20 = tanhf_(pre20); v21 = tanhf_(pre21);
        } else {
            v10 = sigf(pre10); v11 = sigf(pre11);
            v20 = sigf(pre20); v21 = sigf(pre21);
        }
        sg1[0][tid] = v10; sg1[1][tid] = v11;
        sg2[0][tid] = v20; sg2[1][tid] = v21;
        __syncthreads();

        // ---- cell phase: one cell per thread (warp-uniform roles)
        bool active = cl_layer ? (t >= 1) : (t < TSTEPS);
        if (active) {
            const float* Gp = cl_layer ? sg2[cl_b] : sg1[cl_b];
            float iv = Gp[cl_m], fv = Gp[cl_m + 64];
            float gv = Gp[cl_m + 128], ov = Gp[cl_m + 192];
            c = fmaf(fv, c, iv * gv);
            float hn = ov * tanhf_(c);
            if (cl_layer) {
                sh2[cl_b][cl_m] = hn;
                h2out[(size_t)(t - 1) * HID] = __float2half(hn);
            } else {
                sh1[cl_b][cl_m] = hn;
            }
        }
        __syncthreads();
    }
}

// ============================================================================
// Output projection: y[r, 0..2] = W_out · h2[r] + b_out, h2 in fp16.
// 8 lanes per row, 16B loads (8 halves each), 3-level shuffle reduction.
// Traffic: 34 MB read (mostly L2-resident) + 3 MB write.
// ============================================================================
__global__ void __launch_bounds__(256) proj_kernel(
    const float* __restrict__ Wout, const float* __restrict__ bout,
    float* __restrict__ y)
{
    __shared__ float sw[3 * 64];
    __shared__ float sb[3];
    const int tid = threadIdx.x;
    if (tid < 192) sw[tid] = Wout[tid];
    if (tid < 3)   sb[tid] = bout[tid];
    __syncthreads();

    int gg = blockIdx.x * 256 + tid;
    int r = gg >> 3;          // row (b*T + t), 262144 rows
    int l = gg & 7;           // 8 lanes per row, 8 halves each
    // 16-byte load = 4 half2
    const uint4 hv = *(const uint4*)((const char*)g_h2 + (size_t)r * 128 + l * 16);
    float2 h0 = __half22float2(*(const __half2*)&hv.x);
    float2 h1 = __half22float2(*(const __half2*)&hv.y);
    float2 h2v = __half22float2(*(const __half2*)&hv.z);
    float2 h3 = __half22float2(*(const __half2*)&hv.w);
    const int k0 = l * 8;
    float a0, a1, a2;
    {
        const float* wr = &sw[k0];
        a0 = wr[0]*h0.x + wr[1]*h0.y + wr[2]*h1.x + wr[3]*h1.y
           + wr[4]*h2v.x + wr[5]*h2v.y + wr[6]*h3.x + wr[7]*h3.y;
        wr = &sw[64 + k0];
        a1 = wr[0]*h0.x + wr[1]*h0.y + wr[2]*h1.x + wr[3]*h1.y
           + wr[4]*h2v.x + wr[5]*h2v.y + wr[6]*h3.x + wr[7]*h3.y;
        wr = &sw[128 + k0];
        a2 = wr[0]*h0.x + wr[1]*h0.y + wr[2]*h1.x + wr[3]*h1.y
           + wr[4]*h2v.x + wr[5]*h2v.y + wr[6]*h3.x + wr[7]*h3.y;
    }
    #pragma unroll
    for (int o = 4; o > 0; o >>= 1) {
        a0 += __shfl_xor_sync(0xffffffffu, a0, o);
        a1 += __shfl_xor_sync(0xffffffffu, a1, o);
        a2 += __shfl_xor_sync(0xffffffffu, a2, o);
    }
    if (l == 0) {
        y[(size_t)r * 3 + 0] = a0 + sb[0];
        y[(size_t)r * 3 + 1] = a1 + sb[1];
        y[(size_t)r * 3 + 2] = a2 + sb[2];
    }
}

extern "C" void kernel_launch(void* const* d_in, const int* in_sizes, int n_in,
                              void* d_out, int out_size)
{
    const float* x    = (const float*)d_in[0];
    const float* Wih0 = (const float*)d_in[1];
    const float* Whh0 = (const float*)d_in[2];
    const float* bih0 = (const float*)d_in[3];
    const float* bhh0 = (const float*)d_in[4];
    const float* Wih1 = (const float*)d_in[5];
    const float* Whh1 = (const float*)d_in[6];
    const float* bih1 = (const float*)d_in[7];
    const float* bhh1 = (const float*)d_in[8];
    const float* Wout = (const float*)d_in[9];
    const float* bout = (const float*)d_in[10];
    float* y = (float*)d_out;

    lstm_fused<<<BATCH / 2, 256>>>(x, Wih0, Whh0, bih0, bhh0,
                                   Wih1, Whh1, bih1, bhh1);
    proj_kernel<<<(BATCH * TSTEPS * 8) / 256, 256>>>(Wout, bout, y);
}

// round 10
// speedup vs baseline: 1.4604x; 1.0787x over previous
#include <cuda_runtime.h>
#include <cstdint>

#define BATCH 256
#define TSTEPS 1024
#define HID 64
#define DIN 3

// Scratch (device globals — no cudaMalloc allowed).
__device__ float g_h2[BATCH * TSTEPS * HID];

typedef unsigned long long u64;

// ---- packed fp32x2 helpers (ptxas never auto-emits FFMA2) ----
__device__ __forceinline__ u64 fma2(u64 a, u64 b, u64 c) {
    u64 d; asm("fma.rn.f32x2 %0, %1, %2, %3;" : "=l"(d) : "l"(a), "l"(b), "l"(c)); return d;
}
__device__ __forceinline__ u64 packf2(float lo, float hi) {
    u64 d; asm("mov.b64 %0, {%1, %2};" : "=l"(d) : "f"(lo), "f"(hi)); return d;
}
__device__ __forceinline__ float2 unpackf2(u64 v) {
    float2 f; asm("mov.b64 {%0, %1}, %2;" : "=f"(f.x), "=f"(f.y) : "l"(v)); return f;
}
// 16B shared load straight into two 64-bit regs
__device__ __forceinline__ void lds2(u64 &a, u64 &b, uint32_t addr) {
    asm volatile("ld.shared.v2.b64 {%0, %1}, [%2];" : "=l"(a), "=l"(b) : "r"(addr));
}

// ---- single-MUFU activations (tanh.approx: max abs err ~2^-11) ----
__device__ __forceinline__ float tanha(float x) {
    float r; asm("tanh.approx.f32 %0, %1;" : "=f"(r) : "f"(x)); return r;
}
__device__ __forceinline__ float siga(float x) {
    return fmaf(0.5f, tanha(0.5f * x), 0.5f);
}

// ============================================================================
// Fused 2-layer LSTM — round-2 champion structure (861us validated), with
// single-MUFU activations. One CTA per 2 sequences, 256 threads.
// Thread j owns gate row j of Whh0, Wih1, Whh1 (all in registers).
// Pipeline: iter t = layer1 step t, layer2 step t-1.
// sh1 = h1[t-1], sh2 = h2[t-2]; gate exchange via smem; 2 barriers/step.
// Cell phase: 256 threads = 256 cells (2 layers x 2 seqs x 64).
// ============================================================================
__global__ void __launch_bounds__(256, 1) lstm_fused(
    const float* __restrict__ x,
    const float* __restrict__ Wih0, const float* __restrict__ Whh0,
    const float* __restrict__ bih0, const float* __restrict__ bhh0,
    const float* __restrict__ Wih1, const float* __restrict__ Whh1,
    const float* __restrict__ bih1, const float* __restrict__ bhh1)
{
    __shared__ __align__(16) float sx[2][TSTEPS * DIN];  // 24 KB
    __shared__ __align__(16) float sh1[2][HID];
    __shared__ __align__(16) float sh2[2][HID];
    __shared__ __align__(16) float sg1[2][256];
    __shared__ __align__(16) float sg2[2][256];
    const int tid = threadIdx.x;
    const int b0 = blockIdx.x * 2;

    // stage both sequences' inputs
    {
        const float4* xs0 = (const float4*)(x + (size_t)b0 * TSTEPS * DIN);
        const float4* xs1 = (const float4*)(x + (size_t)(b0 + 1) * TSTEPS * DIN);
        #pragma unroll
        for (int i = 0; i < 3; i++) {
            int idx = tid + i * 256;
            ((float4*)sx[0])[idx] = xs0[idx];
            ((float4*)sx[1])[idx] = xs1[idx];
        }
    }

    // per-thread weight rows, packed f32x2 along k
    u64 w0[32], wA[32], wB[32];
    {
        const float4* r0 = (const float4*)(Whh0 + tid * HID);
        const float4* rA = (const float4*)(Wih1 + tid * HID);
        const float4* rB = (const float4*)(Whh1 + tid * HID);
        #pragma unroll
        for (int i = 0; i < 16; i++) {
            float4 v = r0[i]; w0[2*i] = packf2(v.x, v.y); w0[2*i+1] = packf2(v.z, v.w);
            float4 a = rA[i]; wA[2*i] = packf2(a.x, a.y); wA[2*i+1] = packf2(a.z, a.w);
            float4 b = rB[i]; wB[2*i] = packf2(b.x, b.y); wB[2*i+1] = packf2(b.z, b.w);
        }
    }
    const float wx0 = Wih0[tid * 3 + 0], wx1 = Wih0[tid * 3 + 1], wx2 = Wih0[tid * 3 + 2];
    const float bias0 = bih0[tid] + bhh0[tid];
    const float bias1 = bih1[tid] + bhh1[tid];
    const int gtype = tid >> 6;

    // cell role: tid -> (layer, seq, m)
    const int cl_layer = tid >> 7;
    const int cl_b = (tid >> 6) & 1;
    const int cl_m = tid & 63;
    float c = 0.0f;

    if (tid < 128) ((float*)sh1)[tid] = 0.0f;
    else           ((float*)sh2)[tid - 128] = 0.0f;

    const uint32_t a_h1s0 = (uint32_t)__cvta_generic_to_shared(&sh1[0][0]);
    const uint32_t a_h1s1 = (uint32_t)__cvta_generic_to_shared(&sh1[1][0]);
    const uint32_t a_h2s0 = (uint32_t)__cvta_generic_to_shared(&sh2[0][0]);
    const uint32_t a_h2s1 = (uint32_t)__cvta_generic_to_shared(&sh2[1][0]);
    float* h2out = &g_h2[(size_t)(b0 + cl_b) * TSTEPS * HID + cl_m];
    __syncthreads();

    #pragma unroll 1
    for (int t = 0; t <= TSTEPS; t++) {
        // ---- gate phase: 6 dot products, 192 fma2, 64 LDS.128 (all broadcast)
        u64 A0 = 0, A1 = 0, B0 = 0, B1 = 0, C0 = 0, C1 = 0;
        #pragma unroll
        for (int kk = 0; kk < 16; kk++) {
            u64 p0, p1, q0, q1, r0, r1, s0, s1;
            lds2(p0, p1, a_h1s0 + kk * 16);
            lds2(q0, q1, a_h1s1 + kk * 16);
            lds2(r0, r1, a_h2s0 + kk * 16);
            lds2(s0, s1, a_h2s1 + kk * 16);
            A0 = fma2(w0[2*kk],     p0, A0);
            A0 = fma2(w0[2*kk + 1], p1, A0);
            A1 = fma2(w0[2*kk],     q0, A1);
            A1 = fma2(w0[2*kk + 1], q1, A1);
            B0 = fma2(wA[2*kk],     p0, B0);
            B0 = fma2(wA[2*kk + 1], p1, B0);
            B1 = fma2(wA[2*kk],     q0, B1);
            B1 = fma2(wA[2*kk + 1], q1, B1);
            C0 = fma2(wB[2*kk],     r0, C0);
            C0 = fma2(wB[2*kk + 1], r1, C0);
            C1 = fma2(wB[2*kk],     s0, C1);
            C1 = fma2(wB[2*kk + 1], s1, C1);
        }
        const int tx = (t < TSTEPS) ? t : (TSTEPS - 1);
        float xa0 = sx[0][tx*3 + 0], xa1 = sx[0][tx*3 + 1], xa2 = sx[0][tx*3 + 2];
        float xb0 = sx[1][tx*3 + 0], xb1 = sx[1][tx*3 + 1], xb2 = sx[1][tx*3 + 2];
        float2 fA0 = unpackf2(A0), fA1 = unpackf2(A1);
        float2 fB0 = unpackf2(B0), fB1 = unpackf2(B1);
        float2 fC0 = unpackf2(C0), fC1 = unpackf2(C1);
        float pre10 = fA0.x + fA0.y + bias0 + wx0*xa0 + wx1*xa1 + wx2*xa2;
        float pre11 = fA1.x + fA1.y + bias0 + wx0*xb0 + wx1*xb1 + wx2*xb2;
        float pre20 = (fB0.x + fB0.y) + (fC0.x + fC0.y) + bias1;
        float pre21 = (fB1.x + fB1.y) + (fC1.x + fC1.y) + bias1;
        float v10, v11, v20, v21;
        if (gtype == 2) {
            v10 = tanha(pre10); v11 = tanha(pre11);
            v20 = tanha(pre20); v21 = tanha(pre21);
        } else {
            v10 = siga(pre10); v11 = siga(pre11);
            v20 = siga(pre20); v21 = siga(pre21);
        }
        sg1[0][tid] = v10; sg1[1][tid] = v11;
        sg2[0][tid] = v20; sg2[1][tid] = v21;
        __syncthreads();

        // ---- cell phase: one cell per thread (warp-uniform roles)
        bool active = cl_layer ? (t >= 1) : (t < TSTEPS);
        if (active) {
            const float* Gp = cl_layer ? sg2[cl_b] : sg1[cl_b];
            float iv = Gp[cl_m], fv = Gp[cl_m + 64];
            float gv = Gp[cl_m + 128], ov = Gp[cl_m + 192];
            c = fmaf(fv, c, iv * gv);
            float hn = ov * tanha(c);
            if (cl_layer) {
                sh2[cl_b][cl_m] = hn;
                h2out[(size_t)(t - 1) * HID] = hn;
            } else {
                sh1[cl_b][cl_m] = hn;
            }
        }
        __syncthreads();
    }
}

// ============================================================================
// Output projection: y[r, 0..2] = W_out · h2[r] + b_out (fp32 h2, champion
// version — latency-bound at ~22us regardless of traffic).
// ============================================================================
__global__ void __launch_bounds__(256) proj_kernel(
    const float* __restrict__ Wout, const float* __restrict__ bout,
    float* __restrict__ y)
{
    __shared__ float sw[3 * 64];
    __shared__ float sb[3];
    const int tid = threadIdx.x;
    if (tid < 192) sw[tid] = Wout[tid];
    if (tid < 3)   sb[tid] = bout[tid];
    __syncthreads();

    int gg = blockIdx.x * 256 + tid;
    int r = gg >> 4;
    int seg = gg & 15;
    float4 v = *(const float4*)&g_h2[(size_t)r * HID + seg * 4];
    int s4 = seg * 4;
    float a0 = sw[s4] * v.x + sw[s4+1] * v.y + sw[s4+2] * v.z + sw[s4+3] * v.w;
    float a1 = sw[64+s4] * v.x + sw[64+s4+1] * v.y + sw[64+s4+2] * v.z + sw[64+s4+3] * v.w;
    float a2 = sw[128+s4] * v.x + sw[128+s4+1] * v.y + sw[128+s4+2] * v.z + sw[128+s4+3] * v.w;
    #pragma unroll
    for (int o = 8; o > 0; o >>= 1) {
        a0 += __shfl_xor_sync(0xffffffffu, a0, o);
        a1 += __shfl_xor_sync(0xffffffffu, a1, o);
        a2 += __shfl_xor_sync(0xffffffffu, a2, o);
    }
    if (seg == 0) {
        y[(size_t)r * 3 + 0] = a0 + sb[0];
        y[(size_t)r * 3 + 1] = a1 + sb[1];
        y[(size_t)r * 3 + 2] = a2 + sb[2];
    }
}

extern "C" void kernel_launch(void* const* d_in, const int* in_sizes, int n_in,
                              void* d_out, int out_size)
{
    const float* x    = (const float*)d_in[0];
    const float* Wih0 = (const float*)d_in[1];
    const float* Whh0 = (const float*)d_in[2];
    const float* bih0 = (const float*)d_in[3];
    const float* bhh0 = (const float*)d_in[4];
    const float* Wih1 = (const float*)d_in[5];
    const float* Whh1 = (const float*)d_in[6];
    const float* bih1 = (const float*)d_in[7];
    const float* bhh1 = (const float*)d_in[8];
    const float* Wout = (const float*)d_in[9];
    const float* bout = (const float*)d_in[10];
    float* y = (float*)d_out;

    lstm_fused<<<BATCH / 2, 256>>>(x, Wih0, Whh0, bih0, bhh0,
                                   Wih1, Whh1, bih1, bhh1);
    proj_kernel<<<(BATCH * TSTEPS * 16) / 256, 256>>>(Wout, bout, y);
}